// round 12
// baseline (speedup 1.0000x reference)
#include <cuda_runtime.h>
#include <cuda_fp16.h>
#include <cstdint>
#include <cstddef>

typedef unsigned long long ull;
typedef unsigned int u32;

#define BB 32
#define TT 1024
#define HH 512
#define GG 2048
#define NCTA 128            // lstm CTAs
#define GPW 256             // GLOBAL h image pitch (words) -> 1024B rows, line-aligned
#define SPW 260             // SMEM h image pitch (words) -> conflict-free LDS

// ---------------- device scratch (allocations are forbidden) ----------------
__device__ __align__(16) float g_xp[(size_t)TT * GG * BB];   // x_proj[t][g][b]
__device__ __align__(16) u32 g_hpk[2][32 * GPW];             // fp16x2 h image [b][k/2]
__device__ __align__(128) unsigned g_flags[NCTA * 8];

// ---------------- helpers ----------------
__device__ __forceinline__ ull fadd2(ull a, ull b) {
    ull d; asm("add.rn.f32x2 %0, %1, %2;" : "=l"(d) : "l"(a), "l"(b)); return d;
}
__device__ __forceinline__ ull pack2(float x, float y) {
    ull d; asm("mov.b64 %0, {%1, %2};" : "=l"(d) : "f"(x), "f"(y)); return d;
}
__device__ __forceinline__ float sigm(float x) { return __fdividef(1.0f, 1.0f + __expf(-x)); }
__device__ __forceinline__ float tanh_(float x) { return 1.0f - __fdividef(2.0f, __expf(2.0f * x) + 1.0f); }

__device__ __forceinline__ u32 smem_u32(const void* p) {
    u32 a; asm("{ .reg .u64 t; cvta.to.shared.u64 t, %1; cvt.u32.u64 %0, t; }" : "=r"(a) : "l"(p)); return a;
}
__device__ __forceinline__ void cp_async16(u32 dst, const void* src) {
    asm volatile("cp.async.cg.shared.global [%0], [%1], 16;" :: "r"(dst), "l"(src));
}
__device__ __forceinline__ u32 pack_hf2(float a, float b) {
    return (u32)__half_as_ushort(__float2half_rn(a))
         | ((u32)__half_as_ushort(__float2half_rn(b)) << 16);
}
__device__ __forceinline__ void mma16816h(float& c0, float& c1, float& c2, float& c3,
                                          u32 a0, u32 a1, u32 a2, u32 a3, u32 b0, u32 b1) {
    asm volatile(
        "mma.sync.aligned.m16n8k16.row.col.f32.f16.f16.f32 "
        "{%0,%1,%2,%3}, {%4,%5,%6,%7}, {%8,%9}, {%0,%1,%2,%3};"
        : "+f"(c0), "+f"(c1), "+f"(c2), "+f"(c3)
        : "r"(a0), "r"(a1), "r"(a2), "r"(a3), "r"(b0), "r"(b1));
}

// =========================================================================
// Kernel 1: HMMA x_proj, fp16 2-term (unchanged from R11 pass). grid (16,256).
// =========================================================================
#define APITCH 36
#define PLW (128 * APITCH)

__global__ __launch_bounds__(256, 1) void xproj_kernel(
    const float* __restrict__ src, const float* __restrict__ Wih,
    const float* __restrict__ bih, const float* __restrict__ bhh,
    const int* __restrict__ lengths)
{
    extern __shared__ u32 smw[];
    u32* Ah = smw;
    u32* Al = smw + PLW;
    u32* Bh = smw + 2 * PLW;

    const int tid = threadIdx.x;
    if (blockIdx.x == 0 && blockIdx.y == 0) {
        uint4 z = {0, 0, 0, 0};
        const int n16 = (int)(sizeof(g_hpk) / 16);
        for (int i = tid; i < n16; i += 256) ((uint4*)g_hpk)[i] = z;
        for (int i = tid; i < NCTA * 8; i += 256) g_flags[i] = 0u;
    }

    const int n0 = blockIdx.y * 128;
    if ((n0 >> 5) >= lengths[0]) return;
    const int g0 = blockIdx.x * 128;
    const int warp = tid >> 5, lane = tid & 31;
    const int wm = warp & 3, wn = warp >> 2;
    const int g_ = lane >> 2, t_ = lane & 3;

    float C[2][8][4];
#pragma unroll
    for (int mt = 0; mt < 2; mt++)
#pragma unroll
        for (int nt = 0; nt < 8; nt++)
#pragma unroll
            for (int r = 0; r < 4; r++) C[mt][nt][r] = 0.0f;

    for (int kc = 0; kc < 8; kc++) {
        const int c0 = kc * 64;
#pragma unroll
        for (int i = 0; i < 8; i++) {
            int idx = tid + i * 256;
            int row = idx >> 4, cq = idx & 15;
            float4 w = *(const float4*)(Wih + (size_t)(g0 + row) * HH + c0 + cq * 4);
            float hx = __half2float(__float2half_rn(w.x));
            float hy = __half2float(__float2half_rn(w.y));
            float hz = __half2float(__float2half_rn(w.z));
            float hw = __half2float(__float2half_rn(w.w));
            *(uint2*)(Ah + row * APITCH + cq * 2) =
                make_uint2(pack_hf2(w.x, w.y), pack_hf2(w.z, w.w));
            *(uint2*)(Al + row * APITCH + cq * 2) =
                make_uint2(pack_hf2(w.x - hx, w.y - hy), pack_hf2(w.z - hz, w.w - hw));
        }
#pragma unroll
        for (int i = 0; i < 8; i++) {
            int idx = tid + i * 256;
            int n = idx >> 4, cq = idx & 15;
            int N = n0 + n, b = N & 31, tt = N >> 5;
            float4 w = *(const float4*)(src + ((size_t)b * TT + tt) * HH + c0 + cq * 4);
            *(uint2*)(Bh + n * APITCH + cq * 2) =
                make_uint2(pack_hf2(w.x, w.y), pack_hf2(w.z, w.w));
        }
        __syncthreads();

#pragma unroll
        for (int kt = 0; kt < 4; kt++) {
            const int wbase = kt * 8 + t_;
            u32 ah[2][4], al[2][4];
#pragma unroll
            for (int mt = 0; mt < 2; mt++) {
                int ra = wm * 32 + mt * 16 + g_;
                ah[mt][0] = Ah[ra * APITCH + wbase];
                ah[mt][1] = Ah[(ra + 8) * APITCH + wbase];
                ah[mt][2] = Ah[ra * APITCH + wbase + 4];
                ah[mt][3] = Ah[(ra + 8) * APITCH + wbase + 4];
                al[mt][0] = Al[ra * APITCH + wbase];
                al[mt][1] = Al[(ra + 8) * APITCH + wbase];
                al[mt][2] = Al[ra * APITCH + wbase + 4];
                al[mt][3] = Al[(ra + 8) * APITCH + wbase + 4];
            }
#pragma unroll
            for (int nt = 0; nt < 8; nt++) {
                int nc = wn * 64 + nt * 8 + g_;
                u32 b0 = Bh[nc * APITCH + wbase];
                u32 b1 = Bh[nc * APITCH + wbase + 4];
#pragma unroll
                for (int mt = 0; mt < 2; mt++) {
                    mma16816h(C[mt][nt][0], C[mt][nt][1], C[mt][nt][2], C[mt][nt][3],
                              ah[mt][0], ah[mt][1], ah[mt][2], ah[mt][3], b0, b1);
                    mma16816h(C[mt][nt][0], C[mt][nt][1], C[mt][nt][2], C[mt][nt][3],
                              al[mt][0], al[mt][1], al[mt][2], al[mt][3], b0, b1);
                }
            }
        }
        __syncthreads();
    }

#pragma unroll
    for (int mt = 0; mt < 2; mt++) {
        int r0 = g0 + wm * 32 + mt * 16 + g_;
        int r1 = r0 + 8;
        float bs0 = bih[r0] + bhh[r0];
        float bs1 = bih[r1] + bhh[r1];
        ull bias0 = pack2(bs0, bs0), bias1 = pack2(bs1, bs1);
#pragma unroll
        for (int nt = 0; nt < 8; nt++) {
            int N = n0 + wn * 64 + nt * 8 + 2 * t_;
            int tt = N >> 5, b = N & 31;
            *(ull*)(g_xp + ((size_t)tt * GG + r0) * BB + b)
                = fadd2(pack2(C[mt][nt][0], C[mt][nt][1]), bias0);
            *(ull*)(g_xp + ((size_t)tt * GG + r1) * BB + b)
                = fadd2(pack2(C[mt][nt][2], C[mt][nt][3]), bias1);
        }
    }
}

// =========================================================================
// Kernel 2: fp16 2-term recurrence, PER-WARP slice dependency.
// Warp kw: polls 16 producer flags, stages its own 4KB slice, MMAs.
// smem: [0: 33280) image (pitch 260), then red[2][8][16][40] double-buffered.
// =========================================================================
#define SM_RED   (32 * SPW * 4)                       // 33280
#define RED_SZ   (8 * 16 * 40)
#define SM_TOT_L (SM_RED + 2 * RED_SZ * 4)            // 74240 B

__global__ __launch_bounds__(256, 1) void lstm_kernel(
    const int* __restrict__ lengths, const float* __restrict__ Whh,
    float* __restrict__ out)
{
    extern __shared__ char smc[];
    const u32 sb = smem_u32(smc);
    const u32* pk = (const u32*)smc;
    float* red_base = (float*)(smc + SM_RED);

    const int tid  = threadIdx.x;
    const int cta  = blockIdx.x;
    const int kw   = tid >> 5;               // warp = K chunk [kw*64, +64)
    const int lane = tid & 31;
    const int g_   = lane >> 2;
    const int t_   = lane & 3;
    const int len0 = lengths[0];

    // ---- prologue: W fragments (hi, lo fp16), rows m = gate*4 + unit
    u32 Ahi[4][4], Alo[4][4];
    {
        const float* p0 = Whh + (size_t)((g_ >> 2) * HH + cta * 4 + (g_ & 3)) * HH;
        const float* p1 = p0 + (size_t)2 * HH * HH;
#pragma unroll
        for (int kt = 0; kt < 4; kt++) {
            int k0 = kw * 64 + kt * 16 + 2 * t_;
            float2 vv[4] = { *(const float2*)(p0 + k0), *(const float2*)(p1 + k0),
                             *(const float2*)(p0 + k0 + 8), *(const float2*)(p1 + k0 + 8) };
#pragma unroll
            for (int r = 0; r < 4; r++) {
                float hx = __half2float(__float2half_rn(vv[r].x));
                float hy = __half2float(__float2half_rn(vv[r].y));
                Ahi[kt][r] = pack_hf2(vv[r].x, vv[r].y);
                Alo[kt][r] = pack_hf2(vv[r].x - hx, vv[r].y - hy);
            }
        }
    }

    // per-warp flag pointer: lanes 0..15 watch producer CTAs [kw*16, kw*16+16)
    const unsigned* watch = &g_flags[((kw << 4) + (lane & 15)) * 8];

    // per-warp staging addresses (loop-invariant)
    const u32 slice_dst = sb + (u32)(lane * SPW + kw * 32) * 4u;
    const int slice_src_off = lane * GPW + kw * 32;

    // updater mapping (tid < 128): ub = batch, uu = unit
    const int ub = tid >> 2, uu = tid & 3;
    int   len = 0;
    float c_r = 0.0f, h_r = 0.0f;
    if (tid < 128) len = lengths[ub];
    const int pub_word = ub * GPW + cta * 2 + (uu >> 1);

    for (int t = 0; t < len0; t++) {
        const int p = t & 1;
        float* red_s = red_base + (t & 1) * RED_SZ;

        // xg prefetch (in flight during poll; updater threads only)
        float xg0 = 0.f, xg1 = 0.f, xg2 = 0.f, xg3 = 0.f;
        if (tid < 128) {
            const float* xp = g_xp + ((size_t)t * GG + cta * 4 + uu) * BB + ub;
            xg0 = xp[0 * HH * BB];
            xg1 = xp[1 * HH * BB];
            xg2 = xp[2 * HH * BB];
            xg3 = xp[3 * HH * BB];
        }

        // ---- per-warp poll: my 16 producers published step t-1
        {
            unsigned v;
            do {
                asm volatile("ld.acquire.gpu.u32 %0, [%1];" : "=r"(v) : "l"(watch) : "memory");
            } while (__any_sync(0xFFFFFFFFu, (lane < 16) && (v < (unsigned)t)));
        }

        // ---- per-warp slice stage: 8 cp.async of 16B per lane (own row)
        {
            const u32* gsrc = g_hpk[p] + slice_src_off;
#pragma unroll
            for (int c = 0; c < 8; c++)
                cp_async16(slice_dst + c * 16, gsrc + c * 4);
            asm volatile("cp.async.commit_group;\ncp.async.wait_group 0;" ::: "memory");
            __syncwarp();
        }

        // ---- 2-term MMA (32 per warp) on own slice
        float C[4][4];
#pragma unroll
        for (int nt = 0; nt < 4; nt++)
#pragma unroll
            for (int r = 0; r < 4; r++) C[nt][r] = 0.0f;

#pragma unroll
        for (int kt = 0; kt < 4; kt++) {
            const int wbase = kw * 32 + kt * 8 + t_;
#pragma unroll
            for (int nt = 0; nt < 4; nt++) {
                const int n = nt * 8 + g_;
                u32 b0 = pk[n * SPW + wbase];
                u32 b1 = pk[n * SPW + wbase + 4];
                mma16816h(C[nt][0], C[nt][1], C[nt][2], C[nt][3],
                          Ahi[kt][0], Ahi[kt][1], Ahi[kt][2], Ahi[kt][3], b0, b1);
                mma16816h(C[nt][0], C[nt][1], C[nt][2], C[nt][3],
                          Alo[kt][0], Alo[kt][1], Alo[kt][2], Alo[kt][3], b0, b1);
            }
        }

        // write k-partials (double-buffered): red[kw][m][40]
        {
            float* rw = red_s + kw * 16 * 40;
#pragma unroll
            for (int nt = 0; nt < 4; nt++) {
                int n = nt * 8 + 2 * t_;
                *(float2*)(rw + g_ * 40 + n)       = make_float2(C[nt][0], C[nt][1]);
                *(float2*)(rw + (g_ + 8) * 40 + n) = make_float2(C[nt][2], C[nt][3]);
            }
        }
        __syncthreads();   // all 8 warps' partials in; collectively all 128 flags seen >= t

        // updaters: reduce, gates, state, publish; warps 4-7 run ahead
        if (tid < 128) {
            float s[4];
#pragma unroll
            for (int gt = 0; gt < 4; gt++) {
                int m = gt * 4 + uu;
                float a0 = 0.f, a1 = 0.f;
#pragma unroll
                for (int w = 0; w < 8; w += 2) {
                    a0 += red_s[(w * 16 + m) * 40 + ub];
                    a1 += red_s[((w + 1) * 16 + m) * 40 + ub];
                }
                s[gt] = a0 + a1;
            }
            float gi_ = sigm(xg0 + s[0]);
            float gf  = sigm(xg1 + s[1]);
            float gg  = tanh_(xg2 + s[2]);
            float go  = sigm(xg3 + s[3]);
            float cn = gf * c_r + gi_ * gg;
            float hn = go * tanh_(cn);
            bool valid = (t < len);
            if (valid) { c_r = cn; h_r = hn; }
            float out_val = valid ? hn : 0.0f;

            // fp16 publish: pair units via shuffle, even-uu lane stores one u32
            u32 hb = (u32)__half_as_ushort(__float2half_rn(h_r));
            u32 pb = __shfl_down_sync(0xFFFFFFFFu, hb, 1);
            if ((uu & 1) == 0)
                g_hpk[1 - p][pub_word] = hb | (pb << 16);

            asm volatile("bar.sync 1, 128;" ::: "memory");
            if (tid == 0) {
                asm volatile("st.release.gpu.u32 [%0], %1;"
                             :: "l"(&g_flags[cta * 8]), "r"((unsigned)(t + 1)) : "memory");
            }
            out[((size_t)t * BB + ub) * HH + cta * 4 + uu] = out_val;
        }
    }

    // zero the out tail (t >= maxlen)
    for (int t = len0 + (tid >> 7); t < TT; t += 2) {
        int r = tid & 127;
        out[((size_t)t * BB + (r >> 2)) * HH + cta * 4 + (r & 3)] = 0.0f;
    }

    // final hT, cT
    if (tid < 128) {
        size_t base = (size_t)TT * BB * HH;
        out[base + (size_t)ub * HH + cta * 4 + uu] = h_r;
        out[base + (size_t)BB * HH + (size_t)ub * HH + cta * 4 + uu] = c_r;
    }
}

// =========================================================================
extern "C" void kernel_launch(void* const* d_in, const int* in_sizes, int n_in,
                              void* d_out, int out_size) {
    const float* src  = (const float*)d_in[0];
    const int*   lens = (const int*)d_in[1];
    const float* Wih  = (const float*)d_in[2];
    const float* Whh  = (const float*)d_in[3];
    const float* bih  = (const float*)d_in[4];
    const float* bhh  = (const float*)d_in[5];
    float* out = (float*)d_out;

    const int smem_xproj = 3 * PLW * 4;          // 55,296 B
    cudaFuncSetAttribute(xproj_kernel, cudaFuncAttributeMaxDynamicSharedMemorySize, smem_xproj);
    cudaFuncSetAttribute(lstm_kernel,  cudaFuncAttributeMaxDynamicSharedMemorySize, SM_TOT_L);

    dim3 grid(16, 256);
    xproj_kernel<<<grid, 256, smem_xproj>>>(src, Wih, bih, bhh, lens);
    lstm_kernel<<<NCTA, 256, SM_TOT_L>>>(lens, Whh, out);
}

// round 13
// speedup vs baseline: 1.1433x; 1.1433x over previous
#include <cuda_runtime.h>
#include <cuda_fp16.h>
#include <cstdint>
#include <cstddef>

typedef unsigned long long ull;
typedef unsigned int u32;

#define BB 32
#define TT 1024
#define HH 512
#define GG 2048
#define NCTA 128            // lstm CTAs
#define SPW 40              // smem image pitch (words per k-pair row) -> conflict-free

// ---------------- device scratch (allocations are forbidden) ----------------
__device__ __align__(16) float g_xp[(size_t)TT * GG * BB];   // x_proj[t][g][b]
// K-MAJOR fp16x2 h image: [phase][k_pair 0..255][b 0..31], rows = 128B lines
__device__ __align__(16) u32 g_hpk[2][256 * 32];
__device__ __align__(128) unsigned g_flags[NCTA * 8];

// ---------------- helpers ----------------
__device__ __forceinline__ ull fadd2(ull a, ull b) {
    ull d; asm("add.rn.f32x2 %0, %1, %2;" : "=l"(d) : "l"(a), "l"(b)); return d;
}
__device__ __forceinline__ ull pack2(float x, float y) {
    ull d; asm("mov.b64 %0, {%1, %2};" : "=l"(d) : "f"(x), "f"(y)); return d;
}
__device__ __forceinline__ float sigm(float x) { return __fdividef(1.0f, 1.0f + __expf(-x)); }
__device__ __forceinline__ float tanh_(float x) { return 1.0f - __fdividef(2.0f, __expf(2.0f * x) + 1.0f); }

__device__ __forceinline__ u32 smem_u32(const void* p) {
    u32 a; asm("{ .reg .u64 t; cvta.to.shared.u64 t, %1; cvt.u32.u64 %0, t; }" : "=r"(a) : "l"(p)); return a;
}
__device__ __forceinline__ void cp_async16(u32 dst, const void* src) {
    asm volatile("cp.async.cg.shared.global [%0], [%1], 16;" :: "r"(dst), "l"(src));
}
__device__ __forceinline__ u32 pack_hf2(float a, float b) {
    return (u32)__half_as_ushort(__float2half_rn(a))
         | ((u32)__half_as_ushort(__float2half_rn(b)) << 16);
}
__device__ __forceinline__ void mma16816h(float& c0, float& c1, float& c2, float& c3,
                                          u32 a0, u32 a1, u32 a2, u32 a3, u32 b0, u32 b1) {
    asm volatile(
        "mma.sync.aligned.m16n8k16.row.col.f32.f16.f16.f32 "
        "{%0,%1,%2,%3}, {%4,%5,%6,%7}, {%8,%9}, {%0,%1,%2,%3};"
        : "+f"(c0), "+f"(c1), "+f"(c2), "+f"(c3)
        : "r"(a0), "r"(a1), "r"(a2), "r"(a3), "r"(b0), "r"(b1));
}

// =========================================================================
// Kernel 1: HMMA x_proj, fp16 2-term (R11-proven). grid (16, 256).
// =========================================================================
#define APITCH 36
#define PLW (128 * APITCH)

__global__ __launch_bounds__(256, 1) void xproj_kernel(
    const float* __restrict__ src, const float* __restrict__ Wih,
    const float* __restrict__ bih, const float* __restrict__ bhh,
    const int* __restrict__ lengths)
{
    extern __shared__ u32 smw[];
    u32* Ah = smw;
    u32* Al = smw + PLW;
    u32* Bh = smw + 2 * PLW;

    const int tid = threadIdx.x;
    if (blockIdx.x == 0 && blockIdx.y == 0) {
        uint4 z = {0, 0, 0, 0};
        const int n16 = (int)(sizeof(g_hpk) / 16);     // 4096
        for (int i = tid; i < n16; i += 256) ((uint4*)g_hpk)[i] = z;
        for (int i = tid; i < NCTA * 8; i += 256) g_flags[i] = 0u;
    }

    const int n0 = blockIdx.y * 128;
    if ((n0 >> 5) >= lengths[0]) return;
    const int g0 = blockIdx.x * 128;
    const int warp = tid >> 5, lane = tid & 31;
    const int wm = warp & 3, wn = warp >> 2;
    const int g_ = lane >> 2, t_ = lane & 3;

    float C[2][8][4];
#pragma unroll
    for (int mt = 0; mt < 2; mt++)
#pragma unroll
        for (int nt = 0; nt < 8; nt++)
#pragma unroll
            for (int r = 0; r < 4; r++) C[mt][nt][r] = 0.0f;

    for (int kc = 0; kc < 8; kc++) {
        const int c0 = kc * 64;
#pragma unroll
        for (int i = 0; i < 8; i++) {
            int idx = tid + i * 256;
            int row = idx >> 4, cq = idx & 15;
            float4 w = *(const float4*)(Wih + (size_t)(g0 + row) * HH + c0 + cq * 4);
            float hx = __half2float(__float2half_rn(w.x));
            float hy = __half2float(__float2half_rn(w.y));
            float hz = __half2float(__float2half_rn(w.z));
            float hw = __half2float(__float2half_rn(w.w));
            *(uint2*)(Ah + row * APITCH + cq * 2) =
                make_uint2(pack_hf2(w.x, w.y), pack_hf2(w.z, w.w));
            *(uint2*)(Al + row * APITCH + cq * 2) =
                make_uint2(pack_hf2(w.x - hx, w.y - hy), pack_hf2(w.z - hz, w.w - hw));
        }
#pragma unroll
        for (int i = 0; i < 8; i++) {
            int idx = tid + i * 256;
            int n = idx >> 4, cq = idx & 15;
            int N = n0 + n, b = N & 31, tt = N >> 5;
            float4 w = *(const float4*)(src + ((size_t)b * TT + tt) * HH + c0 + cq * 4);
            *(uint2*)(Bh + n * APITCH + cq * 2) =
                make_uint2(pack_hf2(w.x, w.y), pack_hf2(w.z, w.w));
        }
        __syncthreads();

#pragma unroll
        for (int kt = 0; kt < 4; kt++) {
            const int wbase = kt * 8 + t_;
            u32 ah[2][4], al[2][4];
#pragma unroll
            for (int mt = 0; mt < 2; mt++) {
                int ra = wm * 32 + mt * 16 + g_;
                ah[mt][0] = Ah[ra * APITCH + wbase];
                ah[mt][1] = Ah[(ra + 8) * APITCH + wbase];
                ah[mt][2] = Ah[ra * APITCH + wbase + 4];
                ah[mt][3] = Ah[(ra + 8) * APITCH + wbase + 4];
                al[mt][0] = Al[ra * APITCH + wbase];
                al[mt][1] = Al[(ra + 8) * APITCH + wbase];
                al[mt][2] = Al[ra * APITCH + wbase + 4];
                al[mt][3] = Al[(ra + 8) * APITCH + wbase + 4];
            }
#pragma unroll
            for (int nt = 0; nt < 8; nt++) {
                int nc = wn * 64 + nt * 8 + g_;
                u32 b0 = Bh[nc * APITCH + wbase];
                u32 b1 = Bh[nc * APITCH + wbase + 4];
#pragma unroll
                for (int mt = 0; mt < 2; mt++) {
                    mma16816h(C[mt][nt][0], C[mt][nt][1], C[mt][nt][2], C[mt][nt][3],
                              ah[mt][0], ah[mt][1], ah[mt][2], ah[mt][3], b0, b1);
                    mma16816h(C[mt][nt][0], C[mt][nt][1], C[mt][nt][2], C[mt][nt][3],
                              al[mt][0], al[mt][1], al[mt][2], al[mt][3], b0, b1);
                }
            }
        }
        __syncthreads();
    }

#pragma unroll
    for (int mt = 0; mt < 2; mt++) {
        int r0 = g0 + wm * 32 + mt * 16 + g_;
        int r1 = r0 + 8;
        float bs0 = bih[r0] + bhh[r0];
        float bs1 = bih[r1] + bhh[r1];
        ull bias0 = pack2(bs0, bs0), bias1 = pack2(bs1, bs1);
#pragma unroll
        for (int nt = 0; nt < 8; nt++) {
            int N = n0 + wn * 64 + nt * 8 + 2 * t_;
            int tt = N >> 5, b = N & 31;
            *(ull*)(g_xp + ((size_t)tt * GG + r0) * BB + b)
                = fadd2(pack2(C[mt][nt][0], C[mt][nt][1]), bias0);
            *(ull*)(g_xp + ((size_t)tt * GG + r1) * BB + b)
                = fadd2(pack2(C[mt][nt][2], C[mt][nt][3]), bias1);
        }
    }
}

// =========================================================================
// Kernel 2: fp16 2-term recurrence, K-MAJOR image, per-warp slice pipeline.
// Warp kw: polls its 16 producers, stages its contiguous 4KB slice, MMAs.
// smem: [0: 40960) image [256][SPW], then red[2][8][16][40] double-buffered.
// =========================================================================
#define SM_RED   (256 * SPW * 4)                      // 40960
#define RED_SZ   (8 * 16 * 40)
#define SM_TOT_L (SM_RED + 2 * RED_SZ * 4)            // 81920 B

__global__ __launch_bounds__(256, 1) void lstm_kernel(
    const int* __restrict__ lengths, const float* __restrict__ Whh,
    float* __restrict__ out)
{
    extern __shared__ char smc[];
    const u32 sb = smem_u32(smc);
    const u32* img = (const u32*)smc;
    float* red_base = (float*)(smc + SM_RED);

    const int tid  = threadIdx.x;
    const int cta  = blockIdx.x;
    const int kw   = tid >> 5;               // warp = K chunk [kw*64, +64)
    const int lane = tid & 31;
    const int g_   = lane >> 2;
    const int t_   = lane & 3;
    const int len0 = lengths[0];

    // ---- prologue: W fragments (hi, lo fp16), rows m = gate*4 + unit
    u32 Ahi[4][4], Alo[4][4];
    {
        const float* p0 = Whh + (size_t)((g_ >> 2) * HH + cta * 4 + (g_ & 3)) * HH;
        const float* p1 = p0 + (size_t)2 * HH * HH;
#pragma unroll
        for (int kt = 0; kt < 4; kt++) {
            int k0 = kw * 64 + kt * 16 + 2 * t_;
            float2 vv[4] = { *(const float2*)(p0 + k0), *(const float2*)(p1 + k0),
                             *(const float2*)(p0 + k0 + 8), *(const float2*)(p1 + k0 + 8) };
#pragma unroll
            for (int r = 0; r < 4; r++) {
                float hx = __half2float(__float2half_rn(vv[r].x));
                float hy = __half2float(__float2half_rn(vv[r].y));
                Ahi[kt][r] = pack_hf2(vv[r].x, vv[r].y);
                Alo[kt][r] = pack_hf2(vv[r].x - hx, vv[r].y - hy);
            }
        }
    }

    // per-warp watch: lane L watches producer CTA kw*16 + (L&15)
    const unsigned* watch = &g_flags[((kw << 4) + (lane & 15)) * 8];

    // per-warp slice staging addresses (contiguous 4KB global block)
    const int srow = kw * 32 + (lane >> 3);        // + i*4 in loop
    const int schk = lane & 7;

    // updater mapping (tid < 128): ub = batch, uu = unit
    const int ub = tid >> 2, uu = tid & 3;
    int   len = 0;
    float c_r = 0.0f, h_r = 0.0f;
    if (tid < 128) len = lengths[ub];
    const int pub_word = (2 * cta + (uu >> 1)) * 32 + ub;   // k-major publish

    for (int t = 0; t < len0; t++) {
        const int p = t & 1;
        float* red_s = red_base + (t & 1) * RED_SZ;

        // xg prefetch (in flight during poll; updater threads only)
        float xg0 = 0.f, xg1 = 0.f, xg2 = 0.f, xg3 = 0.f;
        if (tid < 128) {
            const float* xp = g_xp + ((size_t)t * GG + cta * 4 + uu) * BB + ub;
            xg0 = xp[0 * HH * BB];
            xg1 = xp[1 * HH * BB];
            xg2 = xp[2 * HH * BB];
            xg3 = xp[3 * HH * BB];
        }

        // ---- per-warp poll: my 16 producers published step t
        if (t > 0) {
            unsigned v;
            do {
                asm volatile("ld.acquire.gpu.u32 %0, [%1];" : "=r"(v) : "l"(watch) : "memory");
            } while (__any_sync(0xFFFFFFFFu, v < (unsigned)t));
        }

        // ---- per-warp slice stage: contiguous, coalesced 512B per step
        {
            const u32* gsrc = g_hpk[p];
#pragma unroll
            for (int i = 0; i < 8; i++) {
                int row = srow + i * 4;
                cp_async16(sb + (u32)(row * SPW + schk * 4) * 4u,
                           gsrc + (size_t)row * 32 + schk * 4);
            }
            asm volatile("cp.async.commit_group;\ncp.async.wait_group 0;" ::: "memory");
            __syncwarp();
        }

        // ---- 2-term MMA (32 per warp) on own slice
        float C[4][4];
#pragma unroll
        for (int nt = 0; nt < 4; nt++)
#pragma unroll
            for (int r = 0; r < 4; r++) C[nt][r] = 0.0f;

#pragma unroll
        for (int kt = 0; kt < 4; kt++) {
            const int r0 = kw * 32 + kt * 8 + t_;
#pragma unroll
            for (int nt = 0; nt < 4; nt++) {
                const int n = nt * 8 + g_;
                u32 b0 = img[r0 * SPW + n];
                u32 b1 = img[(r0 + 4) * SPW + n];
                mma16816h(C[nt][0], C[nt][1], C[nt][2], C[nt][3],
                          Ahi[kt][0], Ahi[kt][1], Ahi[kt][2], Ahi[kt][3], b0, b1);
                mma16816h(C[nt][0], C[nt][1], C[nt][2], C[nt][3],
                          Alo[kt][0], Alo[kt][1], Alo[kt][2], Alo[kt][3], b0, b1);
            }
        }

        // write k-partials (double-buffered): red[kw][m][40]
        {
            float* rw = red_s + kw * 16 * 40;
#pragma unroll
            for (int nt = 0; nt < 4; nt++) {
                int n = nt * 8 + 2 * t_;
                *(float2*)(rw + g_ * 40 + n)       = make_float2(C[nt][0], C[nt][1]);
                *(float2*)(rw + (g_ + 8) * 40 + n) = make_float2(C[nt][2], C[nt][3]);
            }
        }
        __syncthreads();   // collectively: all 128 flags observed >= t before publish

        // updaters: reduce, gates, state, coalesced k-major publish
        if (tid < 128) {
            float s[4];
#pragma unroll
            for (int gt = 0; gt < 4; gt++) {
                int m = gt * 4 + uu;
                float a0 = 0.f, a1 = 0.f;
#pragma unroll
                for (int w = 0; w < 8; w += 2) {
                    a0 += red_s[(w * 16 + m) * 40 + ub];
                    a1 += red_s[((w + 1) * 16 + m) * 40 + ub];
                }
                s[gt] = a0 + a1;
            }
            float gi_ = sigm(xg0 + s[0]);
            float gf  = sigm(xg1 + s[1]);
            float gg  = tanh_(xg2 + s[2]);
            float go  = sigm(xg3 + s[3]);
            float cn = gf * c_r + gi_ * gg;
            float hn = go * tanh_(cn);
            bool valid = (t < len);
            if (valid) { c_r = cn; h_r = hn; }
            float out_val = valid ? hn : 0.0f;

            // fp16 publish: pair adjacent units via shuffle; even-uu lane stores
            u32 hb = (u32)__half_as_ushort(__float2half_rn(h_r));
            u32 pb = __shfl_xor_sync(0xFFFFFFFFu, hb, 1);
            if ((uu & 1) == 0)
                g_hpk[1 - p][pub_word] = hb | (pb << 16);   // 2 coalesced lines/CTA

            asm volatile("bar.sync 1, 128;" ::: "memory");
            if (tid == 0) {
                asm volatile("st.release.gpu.u32 [%0], %1;"
                             :: "l"(&g_flags[cta * 8]), "r"((unsigned)(t + 1)) : "memory");
            }
            out[((size_t)t * BB + ub) * HH + cta * 4 + uu] = out_val;
        }
    }

    // zero the out tail (t >= maxlen)
    for (int t = len0 + (tid >> 7); t < TT; t += 2) {
        int r = tid & 127;
        out[((size_t)t * BB + (r >> 2)) * HH + cta * 4 + (r & 3)] = 0.0f;
    }

    // final hT, cT
    if (tid < 128) {
        size_t base = (size_t)TT * BB * HH;
        out[base + (size_t)ub * HH + cta * 4 + uu] = h_r;
        out[base + (size_t)BB * HH + (size_t)ub * HH + cta * 4 + uu] = c_r;
    }
}

// =========================================================================
extern "C" void kernel_launch(void* const* d_in, const int* in_sizes, int n_in,
                              void* d_out, int out_size) {
    const float* src  = (const float*)d_in[0];
    const int*   lens = (const int*)d_in[1];
    const float* Wih  = (const float*)d_in[2];
    const float* Whh  = (const float*)d_in[3];
    const float* bih  = (const float*)d_in[4];
    const float* bhh  = (const float*)d_in[5];
    float* out = (float*)d_out;

    const int smem_xproj = 3 * PLW * 4;          // 55,296 B
    cudaFuncSetAttribute(xproj_kernel, cudaFuncAttributeMaxDynamicSharedMemorySize, smem_xproj);
    cudaFuncSetAttribute(lstm_kernel,  cudaFuncAttributeMaxDynamicSharedMemorySize, SM_TOT_L);

    dim3 grid(16, 256);
    xproj_kernel<<<grid, 256, smem_xproj>>>(src, Wih, bih, bhh, lens);
    lstm_kernel<<<NCTA, 256, SM_TOT_L>>>(lens, Whh, out);
}

// round 14
// speedup vs baseline: 1.4454x; 1.2642x over previous
#include <cuda_runtime.h>
#include <cuda_fp16.h>
#include <cstdint>
#include <cstddef>

typedef unsigned long long ull;
typedef unsigned int u32;

#define BB 32
#define TT 1024
#define HH 512
#define GG 2048
#define NCTA 128            // lstm CTAs
#define PKP 260             // h image pitch in u32 words (256 data + 4 pad)
#define IMG_B (32 * PKP * 4)    // 33280 bytes per phase

// ---------------- device scratch (allocations are forbidden) ----------------
__device__ __align__(16) float g_xp[(size_t)TT * GG * BB];   // x_proj[t][g][b]
__device__ __align__(16) u32 g_hpk[2][32 * PKP];             // fp16x2 h image [b][k/2]
__device__ __align__(128) unsigned g_flags[NCTA * 8];

// ---------------- helpers ----------------
__device__ __forceinline__ ull fadd2(ull a, ull b) {
    ull d; asm("add.rn.f32x2 %0, %1, %2;" : "=l"(d) : "l"(a), "l"(b)); return d;
}
__device__ __forceinline__ ull pack2(float x, float y) {
    ull d; asm("mov.b64 %0, {%1, %2};" : "=l"(d) : "f"(x), "f"(y)); return d;
}
__device__ __forceinline__ float sigm(float x) { return __fdividef(1.0f, 1.0f + __expf(-x)); }
__device__ __forceinline__ float tanh_(float x) { return 1.0f - __fdividef(2.0f, __expf(2.0f * x) + 1.0f); }

__device__ __forceinline__ u32 smem_u32(const void* p) {
    u32 a; asm("{ .reg .u64 t; cvta.to.shared.u64 t, %1; cvt.u32.u64 %0, t; }" : "=r"(a) : "l"(p)); return a;
}
__device__ __forceinline__ void cp_async16(u32 dst, const void* src) {
    asm volatile("cp.async.cg.shared.global [%0], [%1], 16;" :: "r"(dst), "l"(src));
}
__device__ __forceinline__ u32 pack_hf2(float a, float b) {
    return (u32)__half_as_ushort(__float2half_rn(a))
         | ((u32)__half_as_ushort(__float2half_rn(b)) << 16);
}
// fp16 mma m16n8k16, f32 accum (baseline sm_80)
__device__ __forceinline__ void mma16816h(float& c0, float& c1, float& c2, float& c3,
                                          u32 a0, u32 a1, u32 a2, u32 a3, u32 b0, u32 b1) {
    asm volatile(
        "mma.sync.aligned.m16n8k16.row.col.f32.f16.f16.f32 "
        "{%0,%1,%2,%3}, {%4,%5,%6,%7}, {%8,%9}, {%0,%1,%2,%3};"
        : "+f"(c0), "+f"(c1), "+f"(c2), "+f"(c3)
        : "r"(a0), "r"(a1), "r"(a2), "r"(a3), "r"(b0), "r"(b1));
}

// =========================================================================
// Kernel 1: HMMA x_proj, fp16 2-term. grid (16, 256).
// NOW 2 CTAs/SM (__launch_bounds__(256,2)) so one CTA's MMA phase hides the
// other's stage phase. smem 2x55KB = 110KB < 228KB.
// =========================================================================
#define APITCH 36
#define PLW (128 * APITCH)

__global__ __launch_bounds__(256, 2) void xproj_kernel(
    const float* __restrict__ src, const float* __restrict__ Wih,
    const float* __restrict__ bih, const float* __restrict__ bhh,
    const int* __restrict__ lengths)
{
    extern __shared__ u32 smw[];
    u32* Ah = smw;
    u32* Al = smw + PLW;
    u32* Bh = smw + 2 * PLW;

    const int tid = threadIdx.x;
    if (blockIdx.x == 0 && blockIdx.y == 0) {
        uint4 z = {0, 0, 0, 0};
        const int n16 = (int)(sizeof(g_hpk) / 16);
        for (int i = tid; i < n16; i += 256) ((uint4*)g_hpk)[i] = z;
        for (int i = tid; i < NCTA * 8; i += 256) g_flags[i] = 0u;
    }

    const int n0 = blockIdx.y * 128;
    if ((n0 >> 5) >= lengths[0]) return;         // whole n-tile past maxlen
    const int g0 = blockIdx.x * 128;
    const int warp = tid >> 5, lane = tid & 31;
    const int wm = warp & 3, wn = warp >> 2;
    const int g_ = lane >> 2, t_ = lane & 3;

    float C[2][8][4];
#pragma unroll
    for (int mt = 0; mt < 2; mt++)
#pragma unroll
        for (int nt = 0; nt < 8; nt++)
#pragma unroll
            for (int r = 0; r < 4; r++) C[mt][nt][r] = 0.0f;

    for (int kc = 0; kc < 8; kc++) {
        const int c0 = kc * 64;
        // stage A = W rows [g0,g0+128) cols [c0,c0+64): hi + lo fp16 planes
#pragma unroll
        for (int i = 0; i < 8; i++) {
            int idx = tid + i * 256;
            int row = idx >> 4, cq = idx & 15;
            float4 w = *(const float4*)(Wih + (size_t)(g0 + row) * HH + c0 + cq * 4);
            float hx = __half2float(__float2half_rn(w.x));
            float hy = __half2float(__float2half_rn(w.y));
            float hz = __half2float(__float2half_rn(w.z));
            float hw = __half2float(__float2half_rn(w.w));
            *(uint2*)(Ah + row * APITCH + cq * 2) =
                make_uint2(pack_hf2(w.x, w.y), pack_hf2(w.z, w.w));
            *(uint2*)(Al + row * APITCH + cq * 2) =
                make_uint2(pack_hf2(w.x - hx, w.y - hy), pack_hf2(w.z - hz, w.w - hw));
        }
        // stage B = src, single fp16 plane
#pragma unroll
        for (int i = 0; i < 8; i++) {
            int idx = tid + i * 256;
            int n = idx >> 4, cq = idx & 15;
            int N = n0 + n, b = N & 31, tt = N >> 5;
            float4 w = *(const float4*)(src + ((size_t)b * TT + tt) * HH + c0 + cq * 4);
            *(uint2*)(Bh + n * APITCH + cq * 2) =
                make_uint2(pack_hf2(w.x, w.y), pack_hf2(w.z, w.w));
        }
        __syncthreads();

#pragma unroll
        for (int kt = 0; kt < 4; kt++) {
            const int wbase = kt * 8 + t_;
            u32 ah[2][4], al[2][4];
#pragma unroll
            for (int mt = 0; mt < 2; mt++) {
                int ra = wm * 32 + mt * 16 + g_;
                ah[mt][0] = Ah[ra * APITCH + wbase];
                ah[mt][1] = Ah[(ra + 8) * APITCH + wbase];
                ah[mt][2] = Ah[ra * APITCH + wbase + 4];
                ah[mt][3] = Ah[(ra + 8) * APITCH + wbase + 4];
                al[mt][0] = Al[ra * APITCH + wbase];
                al[mt][1] = Al[(ra + 8) * APITCH + wbase];
                al[mt][2] = Al[ra * APITCH + wbase + 4];
                al[mt][3] = Al[(ra + 8) * APITCH + wbase + 4];
            }
#pragma unroll
            for (int nt = 0; nt < 8; nt++) {
                int nc = wn * 64 + nt * 8 + g_;
                u32 b0 = Bh[nc * APITCH + wbase];
                u32 b1 = Bh[nc * APITCH + wbase + 4];
#pragma unroll
                for (int mt = 0; mt < 2; mt++) {
                    mma16816h(C[mt][nt][0], C[mt][nt][1], C[mt][nt][2], C[mt][nt][3],
                              ah[mt][0], ah[mt][1], ah[mt][2], ah[mt][3], b0, b1);
                    mma16816h(C[mt][nt][0], C[mt][nt][1], C[mt][nt][2], C[mt][nt][3],
                              al[mt][0], al[mt][1], al[mt][2], al[mt][3], b0, b1);
                }
            }
        }
        __syncthreads();
    }

    // epilogue: + (b_ih + b_hh), store pairs to g_xp[t][g][b]
#pragma unroll
    for (int mt = 0; mt < 2; mt++) {
        int r0 = g0 + wm * 32 + mt * 16 + g_;
        int r1 = r0 + 8;
        float bs0 = bih[r0] + bhh[r0];
        float bs1 = bih[r1] + bhh[r1];
        ull bias0 = pack2(bs0, bs0), bias1 = pack2(bs1, bs1);
#pragma unroll
        for (int nt = 0; nt < 8; nt++) {
            int N = n0 + wn * 64 + nt * 8 + 2 * t_;
            int tt = N >> 5, b = N & 31;
            *(ull*)(g_xp + ((size_t)tt * GG + r0) * BB + b)
                = fadd2(pack2(C[mt][nt][0], C[mt][nt][1]), bias0);
            *(ull*)(g_xp + ((size_t)tt * GG + r1) * BB + b)
                = fadd2(pack2(C[mt][nt][2], C[mt][nt][3]), bias1);
        }
    }
}

// =========================================================================
// Kernel 2: fp16 2-term HMMA recurrence — EXACT R11 champion (2892us).
// 128 CTAs x 256 thr, M=16; h image: single fp16 plane (33 KB), cp.async.
// =========================================================================
#define SM_RED  IMG_B
#define SM_TOT_L (SM_RED + 8 * 16 * 40 * 4)     // 53,760 B

__global__ __launch_bounds__(256, 1) void lstm_kernel(
    const int* __restrict__ lengths, const float* __restrict__ Whh,
    float* __restrict__ out)
{
    extern __shared__ char smc[];
    const u32 sb = smem_u32(smc);
    const u32* pk = (const u32*)smc;
    float* red_s = (float*)(smc + SM_RED);

    const int tid  = threadIdx.x;
    const int cta  = blockIdx.x;
    const int kw   = tid >> 5;               // warp = K chunk [kw*64, +64)
    const int lane = tid & 31;
    const int g_   = lane >> 2;
    const int t_   = lane & 3;
    const int len0 = lengths[0];             // max length (sorted desc)

    // ---- prologue: W fragments (hi, lo fp16), rows m = gate*4 + unit
    u32 Ahi[4][4], Alo[4][4];
    {
        const float* p0 = Whh + (size_t)((g_ >> 2) * HH + cta * 4 + (g_ & 3)) * HH;
        const float* p1 = p0 + (size_t)2 * HH * HH;   // rows +8 => gates 2,3
#pragma unroll
        for (int kt = 0; kt < 4; kt++) {
            int k0 = kw * 64 + kt * 16 + 2 * t_;
            float2 vv[4] = { *(const float2*)(p0 + k0), *(const float2*)(p1 + k0),
                             *(const float2*)(p0 + k0 + 8), *(const float2*)(p1 + k0 + 8) };
#pragma unroll
            for (int r = 0; r < 4; r++) {
                float hx = __half2float(__float2half_rn(vv[r].x));
                float hy = __half2float(__float2half_rn(vv[r].y));
                Ahi[kt][r] = pack_hf2(vv[r].x, vv[r].y);
                Alo[kt][r] = pack_hf2(vv[r].x - hx, vv[r].y - hy);
            }
        }
    }

    // updater mapping (tid < 128): ub = batch, uu = unit
    const int ub = tid >> 2, uu = tid & 3;
    int   len = 0;
    float c_r = 0.0f, h_r = 0.0f;
    if (tid < 128) len = lengths[ub];
    const int pub_word = ub * PKP + cta * 2 + (uu >> 1);   // u32 index (pair of units)

    for (int t = 0; t < len0; t++) {
        const int p = t & 1;

        // xg prefetch (in flight during poll)
        float xg0 = 0.f, xg1 = 0.f, xg2 = 0.f, xg3 = 0.f;
        if (tid < 128) {
            const float* xp = g_xp + ((size_t)t * GG + cta * 4 + uu) * BB + ub;
            xg0 = xp[0 * HH * BB];
            xg1 = xp[1 * HH * BB];
            xg2 = xp[2 * HH * BB];
            xg3 = xp[3 * HH * BB];
        }

        // grid barrier: all 128 CTAs published step t-1
        if (t > 0 && tid < NCTA) {
            const unsigned* f = &g_flags[tid * 8];
            unsigned v;
            do {
                asm volatile("ld.acquire.gpu.u32 %0, [%1];" : "=r"(v) : "l"(f) : "memory");
            } while (v < (unsigned)t);
        }
        __syncthreads();

        // stage h image (33 KB, single plane, one wait)
        const u32* hsrc = g_hpk[p];
#pragma unroll
        for (int i = 0; i < 9; i++) {
            int idx = tid + i * 256;
            if (idx < (32 * PKP) / 4)
                cp_async16(sb + idx * 16, hsrc + idx * 4);
        }
        asm volatile("cp.async.commit_group;\ncp.async.wait_group 0;" ::: "memory");
        __syncthreads();

        // ---- 2-term MMA: 32 mma per warp
        float C[4][4];
#pragma unroll
        for (int nt = 0; nt < 4; nt++)
#pragma unroll
            for (int r = 0; r < 4; r++) C[nt][r] = 0.0f;

#pragma unroll
        for (int kt = 0; kt < 4; kt++) {
            const int wbase = kw * 32 + kt * 8 + t_;
#pragma unroll
            for (int nt = 0; nt < 4; nt++) {
                const int n = nt * 8 + g_;
                u32 b0 = pk[n * PKP + wbase];
                u32 b1 = pk[n * PKP + wbase + 4];
                mma16816h(C[nt][0], C[nt][1], C[nt][2], C[nt][3],
                          Ahi[kt][0], Ahi[kt][1], Ahi[kt][2], Ahi[kt][3], b0, b1);
                mma16816h(C[nt][0], C[nt][1], C[nt][2], C[nt][3],
                          Alo[kt][0], Alo[kt][1], Alo[kt][2], Alo[kt][3], b0, b1);
            }
        }

        // write k-partials: red[kw][m][40]
        {
            float* rw = red_s + kw * 16 * 40;
#pragma unroll
            for (int nt = 0; nt < 4; nt++) {
                int n = nt * 8 + 2 * t_;
                *(float2*)(rw + g_ * 40 + n)       = make_float2(C[nt][0], C[nt][1]);
                *(float2*)(rw + (g_ + 8) * 40 + n) = make_float2(C[nt][2], C[nt][3]);
            }
        }
        __syncthreads();

        // updaters: reduce 8 k-partials, gates, state, paired fp16 publish
        if (tid < 128) {
            float s[4];
#pragma unroll
            for (int gt = 0; gt < 4; gt++) {
                int m = gt * 4 + uu;
                float a0 = 0.f, a1 = 0.f;
#pragma unroll
                for (int w = 0; w < 8; w += 2) {
                    a0 += red_s[(w * 16 + m) * 40 + ub];
                    a1 += red_s[((w + 1) * 16 + m) * 40 + ub];
                }
                s[gt] = a0 + a1;
            }
            float gi_ = sigm(xg0 + s[0]);
            float gf  = sigm(xg1 + s[1]);
            float gg  = tanh_(xg2 + s[2]);
            float go  = sigm(xg3 + s[3]);
            float cn = gf * c_r + gi_ * gg;
            float hn = go * tanh_(cn);
            bool valid = (t < len);
            if (valid) { c_r = cn; h_r = hn; }
            float out_val = valid ? hn : 0.0f;

            // fp16 publish: pair units via shuffle, even-uu lane stores one u32
            u32 hb = (u32)__half_as_ushort(__float2half_rn(h_r));
            u32 pb = __shfl_down_sync(0xFFFFFFFFu, hb, 1);
            if ((uu & 1) == 0)
                g_hpk[1 - p][pub_word] = hb | (pb << 16);

            // updater-warps-only barrier, then release (MMA warps not held)
            asm volatile("bar.sync 1, 128;" ::: "memory");
            if (tid == 0) {
                asm volatile("st.release.gpu.u32 [%0], %1;"
                             :: "l"(&g_flags[cta * 8]), "r"((unsigned)(t + 1)) : "memory");
            }
            out[((size_t)t * BB + ub) * HH + cta * 4 + uu] = out_val;
        }
    }

    // zero the out tail (t >= maxlen): pad region of pad_packed output
    for (int t = len0 + (tid >> 7); t < TT; t += 2) {
        int r = tid & 127;
        out[((size_t)t * BB + (r >> 2)) * HH + cta * 4 + (r & 3)] = 0.0f;
    }

    // final hT, cT
    if (tid < 128) {
        size_t base = (size_t)TT * BB * HH;
        out[base + (size_t)ub * HH + cta * 4 + uu] = h_r;
        out[base + (size_t)BB * HH + (size_t)ub * HH + cta * 4 + uu] = c_r;
    }
}

// =========================================================================
extern "C" void kernel_launch(void* const* d_in, const int* in_sizes, int n_in,
                              void* d_out, int out_size) {
    const float* src  = (const float*)d_in[0];
    const int*   lens = (const int*)d_in[1];
    const float* Wih  = (const float*)d_in[2];
    const float* Whh  = (const float*)d_in[3];
    const float* bih  = (const float*)d_in[4];
    const float* bhh  = (const float*)d_in[5];
    float* out = (float*)d_out;

    const int smem_xproj = 3 * PLW * 4;          // 55,296 B per CTA
    cudaFuncSetAttribute(xproj_kernel, cudaFuncAttributeMaxDynamicSharedMemorySize, smem_xproj);
    cudaFuncSetAttribute(lstm_kernel,  cudaFuncAttributeMaxDynamicSharedMemorySize, SM_TOT_L);

    dim3 grid(16, 256);
    xproj_kernel<<<grid, 256, smem_xproj>>>(src, Wih, bih, bhh, lens);
    lstm_kernel<<<NCTA, 256, SM_TOT_L>>>(lens, Whh, out);
}

// round 15
// speedup vs baseline: 1.7264x; 1.1944x over previous
#include <cuda_runtime.h>
#include <cuda_fp16.h>
#include <cstdint>
#include <cstddef>

typedef unsigned long long ull;
typedef unsigned int u32;

#define BB 32
#define TT 1024
#define HH 512
#define GG 2048
#define NCTA 128            // lstm CTAs
#define PKP 260             // h image pitch in u32 words (256 data + 4 pad)
#define IMG_B (32 * PKP * 4)    // 33280 bytes per phase

// ---------------- device scratch (allocations are forbidden) ----------------
__device__ __align__(16) float g_xp[(size_t)TT * GG * BB];   // x_proj[t][g][b]
__device__ __align__(16) u32 g_hpk[2][32 * PKP];             // fp16x2 h image [b][k/2]
__device__ __align__(128) unsigned g_flags[NCTA * 8];

// ---------------- helpers ----------------
__device__ __forceinline__ ull fadd2(ull a, ull b) {
    ull d; asm("add.rn.f32x2 %0, %1, %2;" : "=l"(d) : "l"(a), "l"(b)); return d;
}
__device__ __forceinline__ ull pack2(float x, float y) {
    ull d; asm("mov.b64 %0, {%1, %2};" : "=l"(d) : "f"(x), "f"(y)); return d;
}
__device__ __forceinline__ float sigm(float x) { return __fdividef(1.0f, 1.0f + __expf(-x)); }
__device__ __forceinline__ float tanh_(float x) { return 1.0f - __fdividef(2.0f, __expf(2.0f * x) + 1.0f); }

__device__ __forceinline__ u32 smem_u32(const void* p) {
    u32 a; asm("{ .reg .u64 t; cvta.to.shared.u64 t, %1; cvt.u32.u64 %0, t; }" : "=r"(a) : "l"(p)); return a;
}
__device__ __forceinline__ void cp_async16(u32 dst, const void* src) {
    asm volatile("cp.async.cg.shared.global [%0], [%1], 16;" :: "r"(dst), "l"(src));
}
__device__ __forceinline__ u32 pack_hf2(float a, float b) {
    return (u32)__half_as_ushort(__float2half_rn(a))
         | ((u32)__half_as_ushort(__float2half_rn(b)) << 16);
}
// fp16 mma m16n8k16, f32 accum (baseline sm_80)
__device__ __forceinline__ void mma16816h(float& c0, float& c1, float& c2, float& c3,
                                          u32 a0, u32 a1, u32 a2, u32 a3, u32 b0, u32 b1) {
    asm volatile(
        "mma.sync.aligned.m16n8k16.row.col.f32.f16.f16.f32 "
        "{%0,%1,%2,%3}, {%4,%5,%6,%7}, {%8,%9}, {%0,%1,%2,%3};"
        : "+f"(c0), "+f"(c1), "+f"(c2), "+f"(c3)
        : "r"(a0), "r"(a1), "r"(a2), "r"(a3), "r"(b0), "r"(b1));
}

// =========================================================================
// Kernel 1: HMMA x_proj, SINGLE-term fp16 (A hi only, B single plane).
// grid (16, 256): 128 g x 128 n per CTA. occ=1 (regs unconstrained).
// =========================================================================
#define APITCH 36
#define PLW (128 * APITCH)

__global__ __launch_bounds__(256, 1) void xproj_kernel(
    const float* __restrict__ src, const float* __restrict__ Wih,
    const float* __restrict__ bih, const float* __restrict__ bhh,
    const int* __restrict__ lengths)
{
    extern __shared__ u32 smw[];
    u32* Ah = smw;
    u32* Bh = smw + PLW;

    const int tid = threadIdx.x;
    if (blockIdx.x == 0 && blockIdx.y == 0) {
        uint4 z = {0, 0, 0, 0};
        const int n16 = (int)(sizeof(g_hpk) / 16);
        for (int i = tid; i < n16; i += 256) ((uint4*)g_hpk)[i] = z;
        for (int i = tid; i < NCTA * 8; i += 256) g_flags[i] = 0u;
    }

    const int n0 = blockIdx.y * 128;
    if ((n0 >> 5) >= lengths[0]) return;         // whole n-tile past maxlen
    const int g0 = blockIdx.x * 128;
    const int warp = tid >> 5, lane = tid & 31;
    const int wm = warp & 3, wn = warp >> 2;
    const int g_ = lane >> 2, t_ = lane & 3;

    float C[2][8][4];
#pragma unroll
    for (int mt = 0; mt < 2; mt++)
#pragma unroll
        for (int nt = 0; nt < 8; nt++)
#pragma unroll
            for (int r = 0; r < 4; r++) C[mt][nt][r] = 0.0f;

    for (int kc = 0; kc < 8; kc++) {
        const int c0 = kc * 64;
        // stage A = W rows [g0,g0+128) cols [c0,c0+64): fp16 hi plane only
#pragma unroll
        for (int i = 0; i < 8; i++) {
            int idx = tid + i * 256;
            int row = idx >> 4, cq = idx & 15;
            float4 w = *(const float4*)(Wih + (size_t)(g0 + row) * HH + c0 + cq * 4);
            *(uint2*)(Ah + row * APITCH + cq * 2) =
                make_uint2(pack_hf2(w.x, w.y), pack_hf2(w.z, w.w));
        }
        // stage B = src, single fp16 plane
#pragma unroll
        for (int i = 0; i < 8; i++) {
            int idx = tid + i * 256;
            int n = idx >> 4, cq = idx & 15;
            int N = n0 + n, b = N & 31, tt = N >> 5;
            float4 w = *(const float4*)(src + ((size_t)b * TT + tt) * HH + c0 + cq * 4);
            *(uint2*)(Bh + n * APITCH + cq * 2) =
                make_uint2(pack_hf2(w.x, w.y), pack_hf2(w.z, w.w));
        }
        __syncthreads();

#pragma unroll
        for (int kt = 0; kt < 4; kt++) {
            const int wbase = kt * 8 + t_;
            u32 ah[2][4];
#pragma unroll
            for (int mt = 0; mt < 2; mt++) {
                int ra = wm * 32 + mt * 16 + g_;
                ah[mt][0] = Ah[ra * APITCH + wbase];
                ah[mt][1] = Ah[(ra + 8) * APITCH + wbase];
                ah[mt][2] = Ah[ra * APITCH + wbase + 4];
                ah[mt][3] = Ah[(ra + 8) * APITCH + wbase + 4];
            }
#pragma unroll
            for (int nt = 0; nt < 8; nt++) {
                int nc = wn * 64 + nt * 8 + g_;
                u32 b0 = Bh[nc * APITCH + wbase];
                u32 b1 = Bh[nc * APITCH + wbase + 4];
#pragma unroll
                for (int mt = 0; mt < 2; mt++) {
                    mma16816h(C[mt][nt][0], C[mt][nt][1], C[mt][nt][2], C[mt][nt][3],
                              ah[mt][0], ah[mt][1], ah[mt][2], ah[mt][3], b0, b1);
                }
            }
        }
        __syncthreads();
    }

    // epilogue: + (b_ih + b_hh), store pairs to g_xp[t][g][b]
#pragma unroll
    for (int mt = 0; mt < 2; mt++) {
        int r0 = g0 + wm * 32 + mt * 16 + g_;
        int r1 = r0 + 8;
        float bs0 = bih[r0] + bhh[r0];
        float bs1 = bih[r1] + bhh[r1];
        ull bias0 = pack2(bs0, bs0), bias1 = pack2(bs1, bs1);
#pragma unroll
        for (int nt = 0; nt < 8; nt++) {
            int N = n0 + wn * 64 + nt * 8 + 2 * t_;
            int tt = N >> 5, b = N & 31;
            *(ull*)(g_xp + ((size_t)tt * GG + r0) * BB + b)
                = fadd2(pack2(C[mt][nt][0], C[mt][nt][1]), bias0);
            *(ull*)(g_xp + ((size_t)tt * GG + r1) * BB + b)
                = fadd2(pack2(C[mt][nt][2], C[mt][nt][3]), bias1);
        }
    }
}

// =========================================================================
// Kernel 2: fp16 2-term HMMA recurrence — EXACT R11 champion (2892us).
// =========================================================================
#define SM_RED  IMG_B
#define SM_TOT_L (SM_RED + 8 * 16 * 40 * 4)     // 53,760 B

__global__ __launch_bounds__(256, 1) void lstm_kernel(
    const int* __restrict__ lengths, const float* __restrict__ Whh,
    float* __restrict__ out)
{
    extern __shared__ char smc[];
    const u32 sb = smem_u32(smc);
    const u32* pk = (const u32*)smc;
    float* red_s = (float*)(smc + SM_RED);

    const int tid  = threadIdx.x;
    const int cta  = blockIdx.x;
    const int kw   = tid >> 5;               // warp = K chunk [kw*64, +64)
    const int lane = tid & 31;
    const int g_   = lane >> 2;
    const int t_   = lane & 3;
    const int len0 = lengths[0];             // max length (sorted desc)

    // ---- prologue: W fragments (hi, lo fp16), rows m = gate*4 + unit
    u32 Ahi[4][4], Alo[4][4];
    {
        const float* p0 = Whh + (size_t)((g_ >> 2) * HH + cta * 4 + (g_ & 3)) * HH;
        const float* p1 = p0 + (size_t)2 * HH * HH;   // rows +8 => gates 2,3
#pragma unroll
        for (int kt = 0; kt < 4; kt++) {
            int k0 = kw * 64 + kt * 16 + 2 * t_;
            float2 vv[4] = { *(const float2*)(p0 + k0), *(const float2*)(p1 + k0),
                             *(const float2*)(p0 + k0 + 8), *(const float2*)(p1 + k0 + 8) };
#pragma unroll
            for (int r = 0; r < 4; r++) {
                float hx = __half2float(__float2half_rn(vv[r].x));
                float hy = __half2float(__float2half_rn(vv[r].y));
                Ahi[kt][r] = pack_hf2(vv[r].x, vv[r].y);
                Alo[kt][r] = pack_hf2(vv[r].x - hx, vv[r].y - hy);
            }
        }
    }

    // updater mapping (tid < 128): ub = batch, uu = unit
    const int ub = tid >> 2, uu = tid & 3;
    int   len = 0;
    float c_r = 0.0f, h_r = 0.0f;
    if (tid < 128) len = lengths[ub];
    const int pub_word = ub * PKP + cta * 2 + (uu >> 1);   // u32 index (pair of units)

    for (int t = 0; t < len0; t++) {
        const int p = t & 1;

        // xg prefetch (in flight during poll)
        float xg0 = 0.f, xg1 = 0.f, xg2 = 0.f, xg3 = 0.f;
        if (tid < 128) {
            const float* xp = g_xp + ((size_t)t * GG + cta * 4 + uu) * BB + ub;
            xg0 = xp[0 * HH * BB];
            xg1 = xp[1 * HH * BB];
            xg2 = xp[2 * HH * BB];
            xg3 = xp[3 * HH * BB];
        }

        // grid barrier: all 128 CTAs published step t-1
        if (t > 0 && tid < NCTA) {
            const unsigned* f = &g_flags[tid * 8];
            unsigned v;
            do {
                asm volatile("ld.acquire.gpu.u32 %0, [%1];" : "=r"(v) : "l"(f) : "memory");
            } while (v < (unsigned)t);
        }
        __syncthreads();

        // stage h image (33 KB, single plane, one wait)
        const u32* hsrc = g_hpk[p];
#pragma unroll
        for (int i = 0; i < 9; i++) {
            int idx = tid + i * 256;
            if (idx < (32 * PKP) / 4)
                cp_async16(sb + idx * 16, hsrc + idx * 4);
        }
        asm volatile("cp.async.commit_group;\ncp.async.wait_group 0;" ::: "memory");
        __syncthreads();

        // ---- 2-term MMA: 32 mma per warp
        float C[4][4];
#pragma unroll
        for (int nt = 0; nt < 4; nt++)
#pragma unroll
            for (int r = 0; r < 4; r++) C[nt][r] = 0.0f;

#pragma unroll
        for (int kt = 0; kt < 4; kt++) {
            const int wbase = kw * 32 + kt * 8 + t_;
#pragma unroll
            for (int nt = 0; nt < 4; nt++) {
                const int n = nt * 8 + g_;
                u32 b0 = pk[n * PKP + wbase];
                u32 b1 = pk[n * PKP + wbase + 4];
                mma16816h(C[nt][0], C[nt][1], C[nt][2], C[nt][3],
                          Ahi[kt][0], Ahi[kt][1], Ahi[kt][2], Ahi[kt][3], b0, b1);
                mma16816h(C[nt][0], C[nt][1], C[nt][2], C[nt][3],
                          Alo[kt][0], Alo[kt][1], Alo[kt][2], Alo[kt][3], b0, b1);
            }
        }

        // write k-partials: red[kw][m][40]
        {
            float* rw = red_s + kw * 16 * 40;
#pragma unroll
            for (int nt = 0; nt < 4; nt++) {
                int n = nt * 8 + 2 * t_;
                *(float2*)(rw + g_ * 40 + n)       = make_float2(C[nt][0], C[nt][1]);
                *(float2*)(rw + (g_ + 8) * 40 + n) = make_float2(C[nt][2], C[nt][3]);
            }
        }
        __syncthreads();

        // updaters: reduce 8 k-partials, gates, state, paired fp16 publish
        if (tid < 128) {
            float s[4];
#pragma unroll
            for (int gt = 0; gt < 4; gt++) {
                int m = gt * 4 + uu;
                float a0 = 0.f, a1 = 0.f;
#pragma unroll
                for (int w = 0; w < 8; w += 2) {
                    a0 += red_s[(w * 16 + m) * 40 + ub];
                    a1 += red_s[((w + 1) * 16 + m) * 40 + ub];
                }
                s[gt] = a0 + a1;
            }
            float gi_ = sigm(xg0 + s[0]);
            float gf  = sigm(xg1 + s[1]);
            float gg  = tanh_(xg2 + s[2]);
            float go  = sigm(xg3 + s[3]);
            float cn = gf * c_r + gi_ * gg;
            float hn = go * tanh_(cn);
            bool valid = (t < len);
            if (valid) { c_r = cn; h_r = hn; }
            float out_val = valid ? hn : 0.0f;

            // fp16 publish: pair units via shuffle, even-uu lane stores one u32
            u32 hb = (u32)__half_as_ushort(__float2half_rn(h_r));
            u32 pb = __shfl_down_sync(0xFFFFFFFFu, hb, 1);
            if ((uu & 1) == 0)
                g_hpk[1 - p][pub_word] = hb | (pb << 16);

            // updater-warps-only barrier, then release (MMA warps not held)
            asm volatile("bar.sync 1, 128;" ::: "memory");
            if (tid == 0) {
                asm volatile("st.release.gpu.u32 [%0], %1;"
                             :: "l"(&g_flags[cta * 8]), "r"((unsigned)(t + 1)) : "memory");
            }
            out[((size_t)t * BB + ub) * HH + cta * 4 + uu] = out_val;
        }
    }

    // zero the out tail (t >= maxlen): pad region of pad_packed output
    for (int t = len0 + (tid >> 7); t < TT; t += 2) {
        int r = tid & 127;
        out[((size_t)t * BB + (r >> 2)) * HH + cta * 4 + (r & 3)] = 0.0f;
    }

    // final hT, cT
    if (tid < 128) {
        size_t base = (size_t)TT * BB * HH;
        out[base + (size_t)ub * HH + cta * 4 + uu] = h_r;
        out[base + (size_t)BB * HH + (size_t)ub * HH + cta * 4 + uu] = c_r;
    }
}

// =========================================================================
extern "C" void kernel_launch(void* const* d_in, const int* in_sizes, int n_in,
                              void* d_out, int out_size) {
    const float* src  = (const float*)d_in[0];
    const int*   lens = (const int*)d_in[1];
    const float* Wih  = (const float*)d_in[2];
    const float* Whh  = (const float*)d_in[3];
    const float* bih  = (const float*)d_in[4];
    const float* bhh  = (const float*)d_in[5];
    float* out = (float*)d_out;

    const int smem_xproj = 2 * PLW * 4;          // 36,864 B
    cudaFuncSetAttribute(xproj_kernel, cudaFuncAttributeMaxDynamicSharedMemorySize, smem_xproj);
    cudaFuncSetAttribute(lstm_kernel,  cudaFuncAttributeMaxDynamicSharedMemorySize, SM_TOT_L);

    dim3 grid(16, 256);
    xproj_kernel<<<grid, 256, smem_xproj>>>(src, Wih, bih, bhh, lens);
    lstm_kernel<<<NCTA, 256, SM_TOT_L>>>(lens, Whh, out);
}